// round 14
// baseline (speedup 1.0000x reference)
#include <cuda_runtime.h>
#include <math.h>

// Problem constants
#define Bb 2
#define Dd 256
#define Hh 8
#define Tt 128
#define Ff 64
#define Cc 512
#define TEc 512
#define Ss 128
#define NROW (Bb * Tt * Ss)   // 32768
#define BT (Bb * Tt)          // 256

// Scratch (no cudaMalloc allowed)
__device__ float    g_time_proj[BT * Cc];
__device__ float    g_table[256 * Cc];
// g_act in MMA-fragment layout:
//   uint4 idx = (m16*64 + k8)*32 + lane ; lane=(m%8)*4+(k%4),
//   regs = (m,k),(m+8,k),(m,k+4),(m+8,k+4)
__device__ unsigned g_act[NROW * Cc];
// g_Wtf in B-pair layout: u32 = (k/8)*4096 + n*8 + (k%4)*2 + ((k/4)%2)
__device__ unsigned g_Wtf[Cc * Cc];

// ---------------------------------------------------------------------------
// helpers
// ---------------------------------------------------------------------------
__device__ __forceinline__ unsigned f2tf(float x) {
    unsigned r;
    asm("cvt.rna.tf32.f32 %0, %1;" : "=r"(r) : "f"(x));
    return r;
}
__device__ __forceinline__ float tanh_fast(float x) {
    float y;
    asm("tanh.approx.f32 %0, %1;" : "=f"(y) : "f"(x));
    return y;
}
__device__ __forceinline__ float silu_fast(float x) {
    return x * (0.5f * tanh_fast(0.5f * x) + 0.5f);
}
__device__ __forceinline__ void mma_tf32(float* c, const unsigned* a, const unsigned* b) {
    asm volatile(
        "mma.sync.aligned.m16n8k8.row.col.f32.tf32.tf32.f32 "
        "{%0,%1,%2,%3}, {%4,%5,%6,%7}, {%8,%9}, {%0,%1,%2,%3};"
        : "+f"(c[0]), "+f"(c[1]), "+f"(c[2]), "+f"(c[3])
        : "r"(a[0]), "r"(a[1]), "r"(a[2]), "r"(a[3]),
          "r"(b[0]), "r"(b[1]));
}
__device__ __forceinline__ void cp16(unsigned sdst, const void* gsrc) {
    asm volatile("cp.async.cg.shared.global [%0], [%1], 16;\n"
                 :: "r"(sdst), "l"(gsrc));
}
#define CP_COMMIT() asm volatile("cp.async.commit_group;\n" ::: "memory")
#define CP_WAIT(n)  asm volatile("cp.async.wait_group %0;\n" :: "n"(n) : "memory")

__device__ __forceinline__ unsigned smem_u32(const void* p) {
    return (unsigned)__cvta_generic_to_shared(p);
}

// ---------------------------------------------------------------------------
// K0 (fused prep): blocks 0..254   -> distance table
//                  blocks 255..318 -> w_out pair-layout tf32 convert
//                  blocks 319..350 -> time_proj GEMV
// ---------------------------------------------------------------------------
__global__ __launch_bounds__(512) void k_prep(const float* __restrict__ w_dist,
                                              const float* __restrict__ b_dist,
                                              const float* __restrict__ W,
                                              const float* __restrict__ temb,
                                              const float* __restrict__ w_time,
                                              const float* __restrict__ b_time) {
    int blk = blockIdx.x;
    if (blk < 255) {
        int dd = blk;               // d = dd-127
        int c  = threadIdx.x;
        float d  = (float)(dd - 127);
        float e0 = log1pf(fmaxf(d, 0.f));
        float e1 = log1pf(fmaxf(-d, 0.f));
        float e2 = (dd == 127) ? 1.f : 0.f;
        g_table[dd * Cc + c] = e0 * w_dist[c] + e1 * w_dist[Cc + c]
                             + e2 * w_dist[2 * Cc + c] + b_dist[c];
    } else if (blk < 319) {
        // pair-layout W convert: thread handles one (k8, n): 8 k-values
        int j  = (blk - 255) * 512 + threadIdx.x;   // 0..32767
        int n  = j & 511;
        int k8 = j >> 9;                             // 0..63
        unsigned s[8];
#pragma unroll
        for (int q = 0; q < 8; q++)
            s[(q & 3) * 2 + (q >> 2)] = f2tf(W[(size_t)(k8 * 8 + q) * Cc + n]);
        uint4* dst = (uint4*)(g_Wtf + (size_t)k8 * 4096 + n * 8);
        dst[0] = make_uint4(s[0], s[1], s[2], s[3]);
        dst[1] = make_uint4(s[4], s[5], s[6], s[7]);
    } else {
        int r0 = (blk - 319) * 8;
        int c  = threadIdx.x;
        __shared__ float s[8][TEc];
        for (int i = threadIdx.x; i < 8 * TEc; i += blockDim.x)
            s[i / TEc][i % TEc] = temb[(r0 + i / TEc) * TEc + (i % TEc)];
        __syncthreads();
        float acc[8];
#pragma unroll
        for (int r = 0; r < 8; r++) acc[r] = b_time[c];
        for (int k = 0; k < TEc; k++) {
            float w = w_time[k * Cc + c];
#pragma unroll
            for (int r = 0; r < 8; r++) acc[r] += s[r][k] * w;
        }
#pragma unroll
        for (int r = 0; r < 8; r++) g_time_proj[(r0 + r) * Cc + c] = acc[r];
    }
}

// ---------------------------------------------------------------------------
// K2: act -> fragment layout. Block = one m16 (16 rows, one bt) x 8 k8-chunks.
// ---------------------------------------------------------------------------
__global__ __launch_bounds__(256) void k_act(const int* __restrict__ pd) {
    __shared__ float s_tp[64];
    __shared__ float s_tb[16][68];
    int m16   = blockIdx.x >> 3;          // 0..2047
    int k8b   = (blockIdx.x & 7) * 8;     // k8 chunk base (0..56)
    int kbase = k8b * 8;                  // 64 k values
    int bt    = m16 >> 3;
    int t = threadIdx.x;
    if (t < 64) s_tp[t] = g_time_proj[bt * Cc + kbase + t];
#pragma unroll
    for (int i = 0; i < 4; i++) {
        int f = t + 256 * i;              // 0..1023
        int r = f >> 6, c = f & 63;
        int d = pd[m16 * 16 + r];
        s_tb[r][c] = g_table[(d + 127) * Cc + kbase + c];
    }
    __syncthreads();
    int kk8 = t >> 5, lane = t & 31;
    int grp = lane >> 2, tig = lane & 3;
    int k1 = kk8 * 8 + tig, k2 = k1 + 4;
    float tp1 = s_tp[k1], tp2 = s_tp[k2];
    uint4 v;
    v.x = f2tf(silu_fast(tp1 + s_tb[grp][k1]));        // (m,   k)
    v.y = f2tf(silu_fast(tp1 + s_tb[grp + 8][k1]));    // (m+8, k)
    v.z = f2tf(silu_fast(tp2 + s_tb[grp][k2]));        // (m,   k+4)
    v.w = f2tf(silu_fast(tp2 + s_tb[grp + 8][k2]));    // (m+8, k+4)
    ((uint4*)g_act)[(m16 * 64 + k8b + kk8) * 32 + lane] = v;
}

// ---------------------------------------------------------------------------
// K3 (FUSED): per block (nblk 0..3, mblk=bt 0..255):
//   Phase 1: R_tile[128 s x 128 c] = act @ w_out  (tf32 TC, 3-stage, BK=16)
//   Phase 1.5: +bias -> tf32 -> smem (B-pair-fragment layout, 2 heads)
//   Phase 2: for (head, dhalf): out[128 d x 128 s] = qk_chunk @ R_head^T
// smem u32 map: [0,16384) R region (stages [0,12288) during phase 1)
//               [16384, 16384+128*68) qk chunk (row-major, pad 68)
// ---------------------------------------------------------------------------
#define FS_STG 4096                       // u32 per stage (A 2048 + B 2048)
#define FS_QK  16384                      // u32 offset of qk buffer
#define QK_LD  68
#define FS_TOT (FS_QK + 128 * QK_LD)      // 25088 u32 = 100352 B

__global__ __launch_bounds__(256, 2) void k_fused(const float* __restrict__ bias,
                                                  const float* __restrict__ qk,
                                                  float* __restrict__ out) {
    extern __shared__ unsigned sh[];
    unsigned sh_u = smem_u32(sh);
    int nblk = blockIdx.x, mblk = blockIdx.y;
    int n0 = nblk * 128;
    int t = threadIdx.x, warp = t >> 5, lane = t & 31;
    int wm = (warp >> 2) * 64, wn = (warp & 3) * 32;
    int grp = lane >> 2, tig = lane & 3;
    int mt = (warp >> 2) * 4;

    // ---------------- Phase 1: R mainloop ----------------
    float acc[4][4][4];
#pragma unroll
    for (int mi = 0; mi < 4; mi++)
#pragma unroll
        for (int ni = 0; ni < 4; ni++)
#pragma unroll
            for (int q = 0; q < 4; q++) acc[mi][ni][q] = 0.f;

    auto prefetch = [&](int st, int K0g) {   // K0g = k/8 base, 2 k8 per stage
#pragma unroll
        for (int i = 0; i < 2; i++) {
            int idx = t + 256 * i;           // 0..511 uint4 units
            int m16l = idx >> 6, k8l = (idx >> 5) & 1, ln = idx & 31;
            cp16(sh_u + (st * FS_STG + ((m16l * 2 + k8l) * 32 + ln) * 4) * 4,
                 g_act + ((size_t)((mblk * 8 + m16l) * 64 + K0g + k8l) * 32 + ln) * 4);
            int k8b = idx >> 8, n4 = idx & 255;
            cp16(sh_u + (st * FS_STG + 2048 + k8b * 1024 + n4 * 4) * 4,
                 g_Wtf + (size_t)(K0g + k8b) * 4096 + n0 * 8 + n4 * 4);
        }
    };

    prefetch(0, 0); CP_COMMIT();
    prefetch(1, 2); CP_COMMIT();

    for (int it = 0; it < 32; it++) {
        CP_WAIT(1);
        __syncthreads();
        if (it + 2 < 32) prefetch((it + 2) % 3, (it + 2) * 2);
        CP_COMMIT();

        const uint4* A4 = (const uint4*)(sh + (it % 3) * FS_STG);
        const uint2* B2 = (const uint2*)(sh + (it % 3) * FS_STG + 2048);
#pragma unroll
        for (int kk8 = 0; kk8 < 2; kk8++) {
            uint4 a[4]; uint2 b2[4];
#pragma unroll
            for (int mi = 0; mi < 4; mi++)
                a[mi] = A4[((mt + mi) * 2 + kk8) * 32 + lane];
#pragma unroll
            for (int ni = 0; ni < 4; ni++)
                b2[ni] = B2[kk8 * 512 + (wn + ni * 8 + grp) * 4 + tig];
#pragma unroll
            for (int mi = 0; mi < 4; mi++)
#pragma unroll
                for (int ni = 0; ni < 4; ni++)
                    mma_tf32(acc[mi][ni], (const unsigned*)&a[mi],
                             (const unsigned*)&b2[ni]);
        }
    }
    __syncthreads();   // all stage reads done before R overwrites region

    // ---------------- Phase 1.5: R -> smem (+bias, tf32) ----------------
    int b = mblk >> 7, tt = mblk & 127;
    unsigned* QKb = sh + FS_QK;

    // R layout: u32 = head*8192 + (f>>3)*1024 + s*8 + (f&3)*2 + ((f>>2)&1)
#pragma unroll
    for (int mi = 0; mi < 4; mi++) {
        int s0 = wm + mi * 16 + grp;
#pragma unroll
        for (int ni = 0; ni < 4; ni++) {
            int cb = wn + ni * 8 + tig * 2;
            float2 bv = *(const float2*)(bias + n0 + cb);
#pragma unroll
            for (int q = 0; q < 4; q++) {
                int s = s0 + 8 * (q >> 1);
                int c = cb + (q & 1);
                int head = c >> 6, f = c & 63;
                sh[head * 8192 + (f >> 3) * 1024 + s * 8 + (f & 3) * 2 + ((f >> 2) & 1)]
                    = f2tf(acc[mi][ni][q] + ((q & 1) ? bv.y : bv.x));
            }
        }
    }

    // stage qk chunk 0 (head_l=0, dh=0): full 128 rows x 64 f
    {
        size_t qb = (size_t)b * 16777216 + (size_t)(2 * nblk) * 8192 + (size_t)tt * 64;
#pragma unroll
        for (int i = 0; i < 8; i++) {
            int idx = t + 256 * i;            // 0..2047 float4
            int m = idx >> 4, kp = (idx & 15) * 4;
            float4 v = *(const float4*)(qk + qb + (size_t)m * 65536 + kp);
            unsigned* dst = &QKb[m * QK_LD + kp];
            dst[0] = f2tf(v.x); dst[1] = f2tf(v.y);
            dst[2] = f2tf(v.z); dst[3] = f2tf(v.w);
        }
    }
    __syncthreads();   // R + qk chunk 0 visible to all

    // ---------------- Phase 2: qk @ R^T per (head, dhalf) ----------------
    const uint2* RB2 = (const uint2*)sh;
#pragma unroll 1
    for (int chunk = 0; chunk < 4; chunk++) {
        int head_l = chunk >> 1, dh = chunk & 1;
        if (chunk > 0) {
            size_t qb = (size_t)b * 16777216 + (size_t)(2 * nblk + head_l) * 8192
                      + (size_t)tt * 64 + (size_t)(dh * 128) * 65536;
            float4 v[8];
#pragma unroll
            for (int i = 0; i < 8; i++) {
                int idx = t + 256 * i;
                v[i] = *(const float4*)(qk + qb + (size_t)(idx >> 4) * 65536 + (idx & 15) * 4);
            }
            __syncthreads();     // prior subGEMM reads of qk buffer done
#pragma unroll
            for (int i = 0; i < 8; i++) {
                int idx = t + 256 * i;
                unsigned* dst = &QKb[(idx >> 4) * QK_LD + (idx & 15) * 4];
                dst[0] = f2tf(v[i].x); dst[1] = f2tf(v[i].y);
                dst[2] = f2tf(v[i].z); dst[3] = f2tf(v[i].w);
            }
            __syncthreads();
        }

        float acc2[4][4][4];
#pragma unroll
        for (int mi = 0; mi < 4; mi++)
#pragma unroll
            for (int ni = 0; ni < 4; ni++)
#pragma unroll
                for (int q = 0; q < 4; q++) acc2[mi][ni][q] = 0.f;

#pragma unroll
        for (int k8 = 0; k8 < 64; k8 += 8) {
            unsigned a[4][4]; uint2 b2[4];
#pragma unroll
            for (int mi = 0; mi < 4; mi++) {
                int r = wm + mi * 16 + grp;
                a[mi][0] = QKb[r * QK_LD + k8 + tig];
                a[mi][1] = QKb[(r + 8) * QK_LD + k8 + tig];
                a[mi][2] = QKb[r * QK_LD + k8 + tig + 4];
                a[mi][3] = QKb[(r + 8) * QK_LD + k8 + tig + 4];
            }
#pragma unroll
            for (int ni = 0; ni < 4; ni++)
                b2[ni] = RB2[head_l * 4096 + (k8 >> 3) * 512 + (wn + ni * 8 + grp) * 4 + tig];
#pragma unroll
            for (int mi = 0; mi < 4; mi++)
#pragma unroll
                for (int ni = 0; ni < 4; ni++)
                    mma_tf32(acc2[mi][ni], a[mi], (const unsigned*)&b2[ni]);
        }

        // out[b, d, h, t, s]: d = dh*128 + local, h = 2*nblk + head_l
        // b-stride = D*H*T*S = 33554432 ; d-stride = H*T*S = 131072
        size_t baseO = (size_t)b * 33554432 + (size_t)(2 * nblk + head_l) * 16384
                     + (size_t)tt * 128 + (size_t)(dh * 128) * 131072;
#pragma unroll
        for (int mi = 0; mi < 4; mi++) {
            int r = wm + mi * 16 + grp;
#pragma unroll
            for (int ni = 0; ni < 4; ni++) {
                int s = wn + ni * 8 + tig * 2;
                float2 v0, v1;
                v0.x = acc2[mi][ni][0]; v0.y = acc2[mi][ni][1];
                v1.x = acc2[mi][ni][2]; v1.y = acc2[mi][ni][3];
                *(float2*)(out + baseO + (size_t)r * 131072 + s) = v0;
                *(float2*)(out + baseO + (size_t)(r + 8) * 131072 + s) = v1;
            }
        }
    }
}

// ---------------------------------------------------------------------------
extern "C" void kernel_launch(void* const* d_in, const int* in_sizes, int n_in,
                              void* d_out, int out_size) {
    const float* qk     = (const float*)d_in[0];
    const float* temb   = (const float*)d_in[1];
    const int*   pd     = (const int*)d_in[2];
    const float* w_dist = (const float*)d_in[3];
    const float* b_dist = (const float*)d_in[4];
    const float* w_time = (const float*)d_in[5];
    const float* b_time = (const float*)d_in[6];
    const float* w_out  = (const float*)d_in[7];
    const float* b_out  = (const float*)d_in[8];
    float* out = (float*)d_out;

    const int fs_smem = FS_TOT * 4;   // 100,352 B -> 2 blocks/SM
    cudaFuncSetAttribute(k_fused, cudaFuncAttributeMaxDynamicSharedMemorySize, fs_smem);

    k_prep<<<351, 512>>>(w_dist, b_dist, w_out, temb, w_time, b_time);
    k_act<<<NROW / 16 * 8, 256>>>(pd);
    k_fused<<<dim3(4, 256), 256, fs_smem>>>(b_out, qk, out);
}

// round 16
// speedup vs baseline: 1.3351x; 1.3351x over previous
#include <cuda_runtime.h>
#include <math.h>

// Problem constants
#define Bb 2
#define Dd 256
#define Hh 8
#define Tt 128
#define Ff 64
#define Cc 512
#define TEc 512
#define Ss 128
#define NROW (Bb * Tt * Ss)   // 32768
#define BT (Bb * Tt)          // 256

// Scratch (no cudaMalloc allowed)
__device__ float    g_time_proj[BT * Cc];
__device__ float    g_tp_part[8][BT * Cc];   // split-K partials (4 MB)
__device__ float    g_table[256 * Cc];
// g_act in MMA-fragment layout:
//   uint4 idx = (m16*64 + k8)*32 + lane ; lane=(m%8)*4+(k%4),
//   regs = (m,k),(m+8,k),(m,k+4),(m+8,k+4)
__device__ unsigned g_act[NROW * Cc];
// g_Wtf in B-pair layout: u32 = (k/8)*4096 + n*8 + (k%4)*2 + ((k/4)%2)
__device__ unsigned g_Wtf[Cc * Cc];

// ---------------------------------------------------------------------------
// helpers
// ---------------------------------------------------------------------------
__device__ __forceinline__ unsigned f2tf(float x) {
    unsigned r;
    asm("cvt.rna.tf32.f32 %0, %1;" : "=r"(r) : "f"(x));
    return r;
}
__device__ __forceinline__ float tanh_fast(float x) {
    float y;
    asm("tanh.approx.f32 %0, %1;" : "=f"(y) : "f"(x));
    return y;
}
__device__ __forceinline__ float silu_fast(float x) {
    return x * (0.5f * tanh_fast(0.5f * x) + 0.5f);
}
__device__ __forceinline__ void mma_tf32(float* c, const unsigned* a, const unsigned* b) {
    asm volatile(
        "mma.sync.aligned.m16n8k8.row.col.f32.tf32.tf32.f32 "
        "{%0,%1,%2,%3}, {%4,%5,%6,%7}, {%8,%9}, {%0,%1,%2,%3};"
        : "+f"(c[0]), "+f"(c[1]), "+f"(c[2]), "+f"(c[3])
        : "r"(a[0]), "r"(a[1]), "r"(a[2]), "r"(a[3]),
          "r"(b[0]), "r"(b[1]));
}
__device__ __forceinline__ void cp16(unsigned sdst, const void* gsrc) {
    asm volatile("cp.async.cg.shared.global [%0], [%1], 16;\n"
                 :: "r"(sdst), "l"(gsrc));
}
#define CP_COMMIT() asm volatile("cp.async.commit_group;\n" ::: "memory")
#define CP_WAIT(n)  asm volatile("cp.async.wait_group %0;\n" :: "n"(n) : "memory")

__device__ __forceinline__ unsigned smem_u32(const void* p) {
    return (unsigned)__cvta_generic_to_shared(p);
}

// ---------------------------------------------------------------------------
// K0 (fused prep): blocks 0..254   -> distance table
//                  blocks 255..318 -> w_out pair-layout tf32 convert
//                  blocks 319..574 -> time_proj split-K partials (32 rg x 8 kc)
// ---------------------------------------------------------------------------
__global__ __launch_bounds__(512) void k_prep(const float* __restrict__ w_dist,
                                              const float* __restrict__ b_dist,
                                              const float* __restrict__ W,
                                              const float* __restrict__ temb,
                                              const float* __restrict__ w_time,
                                              const float* __restrict__ b_time) {
    int blk = blockIdx.x;
    if (blk < 255) {
        int dd = blk;               // d = dd-127
        int c  = threadIdx.x;
        float d  = (float)(dd - 127);
        float e0 = log1pf(fmaxf(d, 0.f));
        float e1 = log1pf(fmaxf(-d, 0.f));
        float e2 = (dd == 127) ? 1.f : 0.f;
        g_table[dd * Cc + c] = e0 * w_dist[c] + e1 * w_dist[Cc + c]
                             + e2 * w_dist[2 * Cc + c] + b_dist[c];
    } else if (blk < 319) {
        // pair-layout W convert: thread handles one (k8, n): 8 k-values
        int j  = (blk - 255) * 512 + threadIdx.x;   // 0..32767
        int n  = j & 511;
        int k8 = j >> 9;                             // 0..63
        unsigned s[8];
#pragma unroll
        for (int q = 0; q < 8; q++)
            s[(q & 3) * 2 + (q >> 2)] = f2tf(W[(size_t)(k8 * 8 + q) * Cc + n]);
        uint4* dst = (uint4*)(g_Wtf + (size_t)k8 * 4096 + n * 8);
        dst[0] = make_uint4(s[0], s[1], s[2], s[3]);
        dst[1] = make_uint4(s[4], s[5], s[6], s[7]);
    } else {
        // time_proj split-K: idx -> (rowgroup rg 0..31, kchunk kc 0..7)
        int idx = blk - 319;
        int rg  = idx >> 3, kc = idx & 7;
        int r0  = rg * 8;
        int k0  = kc * 64;
        int c   = threadIdx.x;
        __shared__ float s[8][64];
        {
            int i = threadIdx.x;          // 512 threads load 8x64 values
            s[i >> 6][i & 63] = temb[(r0 + (i >> 6)) * TEc + k0 + (i & 63)];
        }
        __syncthreads();
        float acc[8];
#pragma unroll
        for (int r = 0; r < 8; r++) acc[r] = 0.f;
#pragma unroll 8
        for (int kk = 0; kk < 64; kk++) {
            float w = w_time[(size_t)(k0 + kk) * Cc + c];
#pragma unroll
            for (int r = 0; r < 8; r++) acc[r] += s[r][kk] * w;
        }
        float bterm = (kc == 0) ? b_time[c] : 0.f;
#pragma unroll
        for (int r = 0; r < 8; r++)
            g_tp_part[kc][(r0 + r) * Cc + c] = acc[r] + bterm;
    }
}

// ---------------------------------------------------------------------------
// K0b: reduce 8 split-K partials -> g_time_proj (deterministic order)
// ---------------------------------------------------------------------------
__global__ __launch_bounds__(256) void k_tpreduce() {
    int i = blockIdx.x * blockDim.x + threadIdx.x;    // over BT*Cc/4
    float4 a = ((const float4*)g_tp_part[0])[i];
#pragma unroll
    for (int p = 1; p < 8; p++) {
        float4 b = ((const float4*)g_tp_part[p])[i];
        a.x += b.x; a.y += b.y; a.z += b.z; a.w += b.w;
    }
    ((float4*)g_time_proj)[i] = a;
}

// ---------------------------------------------------------------------------
// K2: act -> fragment layout. Block = one m16 (16 rows, one bt) x 8 k8-chunks.
// ---------------------------------------------------------------------------
__global__ __launch_bounds__(256) void k_act(const int* __restrict__ pd) {
    __shared__ float s_tp[64];
    __shared__ float s_tb[16][68];
    int m16   = blockIdx.x >> 3;          // 0..2047
    int k8b   = (blockIdx.x & 7) * 8;     // k8 chunk base (0..56)
    int kbase = k8b * 8;                  // 64 k values
    int bt    = m16 >> 3;
    int t = threadIdx.x;
    if (t < 64) s_tp[t] = g_time_proj[bt * Cc + kbase + t];
#pragma unroll
    for (int i = 0; i < 4; i++) {
        int f = t + 256 * i;              // 0..1023
        int r = f >> 6, c = f & 63;
        int d = pd[m16 * 16 + r];
        s_tb[r][c] = g_table[(d + 127) * Cc + kbase + c];
    }
    __syncthreads();
    int kk8 = t >> 5, lane = t & 31;
    int grp = lane >> 2, tig = lane & 3;
    int k1 = kk8 * 8 + tig, k2 = k1 + 4;
    float tp1 = s_tp[k1], tp2 = s_tp[k2];
    uint4 v;
    v.x = f2tf(silu_fast(tp1 + s_tb[grp][k1]));        // (m,   k)
    v.y = f2tf(silu_fast(tp1 + s_tb[grp + 8][k1]));    // (m+8, k)
    v.z = f2tf(silu_fast(tp2 + s_tb[grp][k2]));        // (m,   k+4)
    v.w = f2tf(silu_fast(tp2 + s_tb[grp + 8][k2]));    // (m+8, k+4)
    ((uint4*)g_act)[(m16 * 64 + k8b + kk8) * 32 + lane] = v;
}

// ---------------------------------------------------------------------------
// K3 (FUSED): per block (nblk 0..3, mblk=bt 0..255):
//   Phase 1: R_tile[128 s x 128 c] = act @ w_out  (tf32 TC, 3-stage, BK=16)
//   Phase 1.5: +bias -> tf32 -> smem (B-pair-fragment layout, 2 heads)
//   Phase 2: for (head, dhalf): out[128 d x 128 s] = qk_chunk @ R_head^T
// smem u32 map: [0,16384) R region (stages [0,12288) during phase 1)
//               [16384, 16384+128*68) qk chunk (row-major, pad 68)
// ---------------------------------------------------------------------------
#define FS_STG 4096                       // u32 per stage (A 2048 + B 2048)
#define FS_QK  16384                      // u32 offset of qk buffer
#define QK_LD  68
#define FS_TOT (FS_QK + 128 * QK_LD)      // 25088 u32 = 100352 B

__global__ __launch_bounds__(256, 2) void k_fused(const float* __restrict__ bias,
                                                  const float* __restrict__ qk,
                                                  float* __restrict__ out) {
    extern __shared__ unsigned sh[];
    unsigned sh_u = smem_u32(sh);
    int nblk = blockIdx.x, mblk = blockIdx.y;
    int n0 = nblk * 128;
    int t = threadIdx.x, warp = t >> 5, lane = t & 31;
    int wm = (warp >> 2) * 64, wn = (warp & 3) * 32;
    int grp = lane >> 2, tig = lane & 3;
    int mt = (warp >> 2) * 4;

    // ---------------- Phase 1: R mainloop ----------------
    float acc[4][4][4];
#pragma unroll
    for (int mi = 0; mi < 4; mi++)
#pragma unroll
        for (int ni = 0; ni < 4; ni++)
#pragma unroll
            for (int q = 0; q < 4; q++) acc[mi][ni][q] = 0.f;

    auto prefetch = [&](int st, int K0g) {   // K0g = k/8 base, 2 k8 per stage
#pragma unroll
        for (int i = 0; i < 2; i++) {
            int idx = t + 256 * i;           // 0..511 uint4 units
            int m16l = idx >> 6, k8l = (idx >> 5) & 1, ln = idx & 31;
            cp16(sh_u + (st * FS_STG + ((m16l * 2 + k8l) * 32 + ln) * 4) * 4,
                 g_act + ((size_t)((mblk * 8 + m16l) * 64 + K0g + k8l) * 32 + ln) * 4);
            int k8b = idx >> 8, n4 = idx & 255;
            cp16(sh_u + (st * FS_STG + 2048 + k8b * 1024 + n4 * 4) * 4,
                 g_Wtf + (size_t)(K0g + k8b) * 4096 + n0 * 8 + n4 * 4);
        }
    };

    prefetch(0, 0); CP_COMMIT();
    prefetch(1, 2); CP_COMMIT();

    for (int it = 0; it < 32; it++) {
        CP_WAIT(1);
        __syncthreads();
        if (it + 2 < 32) prefetch((it + 2) % 3, (it + 2) * 2);
        CP_COMMIT();

        const uint4* A4 = (const uint4*)(sh + (it % 3) * FS_STG);
        const uint2* B2 = (const uint2*)(sh + (it % 3) * FS_STG + 2048);
#pragma unroll
        for (int kk8 = 0; kk8 < 2; kk8++) {
            uint4 a[4]; uint2 b2[4];
#pragma unroll
            for (int mi = 0; mi < 4; mi++)
                a[mi] = A4[((mt + mi) * 2 + kk8) * 32 + lane];
#pragma unroll
            for (int ni = 0; ni < 4; ni++)
                b2[ni] = B2[kk8 * 512 + (wn + ni * 8 + grp) * 4 + tig];
#pragma unroll
            for (int mi = 0; mi < 4; mi++)
#pragma unroll
                for (int ni = 0; ni < 4; ni++)
                    mma_tf32(acc[mi][ni], (const unsigned*)&a[mi],
                             (const unsigned*)&b2[ni]);
        }
    }
    __syncthreads();   // all stage reads done before R overwrites region

    // ---------------- Phase 1.5: R -> smem (+bias, tf32) ----------------
    int b = mblk >> 7, tt = mblk & 127;
    unsigned* QKb = sh + FS_QK;

    // R layout: u32 = head*8192 + (f>>3)*1024 + s*8 + (f&3)*2 + ((f>>2)&1)
#pragma unroll
    for (int mi = 0; mi < 4; mi++) {
        int s0 = wm + mi * 16 + grp;
#pragma unroll
        for (int ni = 0; ni < 4; ni++) {
            int cb = wn + ni * 8 + tig * 2;
            float2 bv = *(const float2*)(bias + n0 + cb);
#pragma unroll
            for (int q = 0; q < 4; q++) {
                int s = s0 + 8 * (q >> 1);
                int c = cb + (q & 1);
                int head = c >> 6, f = c & 63;
                sh[head * 8192 + (f >> 3) * 1024 + s * 8 + (f & 3) * 2 + ((f >> 2) & 1)]
                    = f2tf(acc[mi][ni][q] + ((q & 1) ? bv.y : bv.x));
            }
        }
    }

    // stage qk chunk 0 (head_l=0, dh=0): full 128 rows x 64 f
    {
        size_t qb = (size_t)b * 16777216 + (size_t)(2 * nblk) * 8192 + (size_t)tt * 64;
#pragma unroll
        for (int i = 0; i < 8; i++) {
            int idx = t + 256 * i;            // 0..2047 float4
            int m = idx >> 4, kp = (idx & 15) * 4;
            float4 v = *(const float4*)(qk + qb + (size_t)m * 65536 + kp);
            unsigned* dst = &QKb[m * QK_LD + kp];
            dst[0] = f2tf(v.x); dst[1] = f2tf(v.y);
            dst[2] = f2tf(v.z); dst[3] = f2tf(v.w);
        }
    }
    __syncthreads();   // R + qk chunk 0 visible to all

    // ---------------- Phase 2: qk @ R^T per (head, dhalf) ----------------
    const uint2* RB2 = (const uint2*)sh;
#pragma unroll 1
    for (int chunk = 0; chunk < 4; chunk++) {
        int head_l = chunk >> 1, dh = chunk & 1;
        if (chunk > 0) {
            size_t qb = (size_t)b * 16777216 + (size_t)(2 * nblk + head_l) * 8192
                      + (size_t)tt * 64 + (size_t)(dh * 128) * 65536;
            float4 v[8];
#pragma unroll
            for (int i = 0; i < 8; i++) {
                int idx = t + 256 * i;
                v[i] = *(const float4*)(qk + qb + (size_t)(idx >> 4) * 65536 + (idx & 15) * 4);
            }
            __syncthreads();     // prior subGEMM reads of qk buffer done
#pragma unroll
            for (int i = 0; i < 8; i++) {
                int idx = t + 256 * i;
                unsigned* dst = &QKb[(idx >> 4) * QK_LD + (idx & 15) * 4];
                dst[0] = f2tf(v[i].x); dst[1] = f2tf(v[i].y);
                dst[2] = f2tf(v[i].z); dst[3] = f2tf(v[i].w);
            }
            __syncthreads();
        }

        float acc2[4][4][4];
#pragma unroll
        for (int mi = 0; mi < 4; mi++)
#pragma unroll
            for (int ni = 0; ni < 4; ni++)
#pragma unroll
                for (int q = 0; q < 4; q++) acc2[mi][ni][q] = 0.f;

#pragma unroll
        for (int k8 = 0; k8 < 64; k8 += 8) {
            unsigned a[4][4]; uint2 b2[4];
#pragma unroll
            for (int mi = 0; mi < 4; mi++) {
                int r = wm + mi * 16 + grp;
                a[mi][0] = QKb[r * QK_LD + k8 + tig];
                a[mi][1] = QKb[(r + 8) * QK_LD + k8 + tig];
                a[mi][2] = QKb[r * QK_LD + k8 + tig + 4];
                a[mi][3] = QKb[(r + 8) * QK_LD + k8 + tig + 4];
            }
#pragma unroll
            for (int ni = 0; ni < 4; ni++)
                b2[ni] = RB2[head_l * 4096 + (k8 >> 3) * 512 + (wn + ni * 8 + grp) * 4 + tig];
#pragma unroll
            for (int mi = 0; mi < 4; mi++)
#pragma unroll
                for (int ni = 0; ni < 4; ni++)
                    mma_tf32(acc2[mi][ni], a[mi], (const unsigned*)&b2[ni]);
        }

        // out[b, d, h, t, s]: d = dh*128 + local, h = 2*nblk + head_l
        // b-stride = D*H*T*S = 33554432 ; d-stride = H*T*S = 131072
        size_t baseO = (size_t)b * 33554432 + (size_t)(2 * nblk + head_l) * 16384
                     + (size_t)tt * 128 + (size_t)(dh * 128) * 131072;
#pragma unroll
        for (int mi = 0; mi < 4; mi++) {
            int r = wm + mi * 16 + grp;
#pragma unroll
            for (int ni = 0; ni < 4; ni++) {
                int s = wn + ni * 8 + tig * 2;
                float2 v0, v1;
                v0.x = acc2[mi][ni][0]; v0.y = acc2[mi][ni][1];
                v1.x = acc2[mi][ni][2]; v1.y = acc2[mi][ni][3];
                *(float2*)(out + baseO + (size_t)r * 131072 + s) = v0;
                *(float2*)(out + baseO + (size_t)(r + 8) * 131072 + s) = v1;
            }
        }
    }
}

// ---------------------------------------------------------------------------
extern "C" void kernel_launch(void* const* d_in, const int* in_sizes, int n_in,
                              void* d_out, int out_size) {
    const float* qk     = (const float*)d_in[0];
    const float* temb   = (const float*)d_in[1];
    const int*   pd     = (const int*)d_in[2];
    const float* w_dist = (const float*)d_in[3];
    const float* b_dist = (const float*)d_in[4];
    const float* w_time = (const float*)d_in[5];
    const float* b_time = (const float*)d_in[6];
    const float* w_out  = (const float*)d_in[7];
    const float* b_out  = (const float*)d_in[8];
    float* out = (float*)d_out;

    const int fs_smem = FS_TOT * 4;   // 100,352 B -> 2 blocks/SM
    cudaFuncSetAttribute(k_fused, cudaFuncAttributeMaxDynamicSharedMemorySize, fs_smem);

    k_prep<<<575, 512>>>(w_dist, b_dist, w_out, temb, w_time, b_time);
    k_tpreduce<<<BT * Cc / 4 / 256, 256>>>();
    k_act<<<NROW / 16 * 8, 256>>>(pd);
    k_fused<<<dim3(4, 256), 256, fs_smem>>>(b_out, qk, out);
}